// round 10
// baseline (speedup 1.0000x reference)
#include <cuda_runtime.h>
#include <cstdint>

// Problem constants
#define LL 1024
#define DM 768
#define NH 12
#define FD 16
#define HD 64
#define CH 64
#define NC 16
#define DP 288           // padded expanded feature dim (273 -> 288)
#define NW 144           // DP/2 packed words
#define QK_WORDS (64*NW) // 9216 words per (h,c): [row64][nw144]
#define K2_WORDS (DP*32) // 9216 words per (h,c): [n288][iw32]
#define V_WORDS  (64*32) // 2048 words per (h,c): [d64][iw32]

// Scratch (static device globals)
__device__ float    g_Q[LL*NH*FD];
__device__ float    g_K[LL*NH*FD];
__device__ float    g_V[LL*DM];
__device__ uint32_t g_Qh [NH*NC*QK_WORDS], g_Ql [NH*NC*QK_WORDS]; // Qf packed along n
__device__ uint32_t g_K1h[NH*NC*QK_WORDS], g_K1l[NH*NC*QK_WORDS]; // Kf packed along n (attn B)
__device__ uint32_t g_K2h[NH*NC*K2_WORDS], g_K2l[NH*NC*K2_WORDS]; // Kf packed along i (kv A)
__device__ uint32_t g_Vh [NH*NC*V_WORDS],  g_Vl [NH*NC*V_WORDS];  // V packed along token
__device__ uint32_t g_Sh [NH*NC*QK_WORDS], g_Sl [NH*NC*QK_WORDS]; // prefix S packed: [d][nw]
__device__ uint32_t g_kh [NH*NC*NW],       g_kl [NH*NC*NW];       // prefix ksum packed
__device__ float    g_Y[LL*DM];

// ---------------------------------------------------------------------------
// bf16 split-pack + mma + ldmatrix helpers
// ---------------------------------------------------------------------------
__device__ __forceinline__ void split_pack(float x0, float x1, uint32_t& hi, uint32_t& lo) {
    uint32_t h;
    asm("cvt.rn.bf16x2.f32 %0, %1, %2;" : "=r"(h) : "f"(x1), "f"(x0));
    float h0 = __uint_as_float(h << 16);
    float h1 = __uint_as_float(h & 0xffff0000u);
    asm("cvt.rn.bf16x2.f32 %0, %1, %2;" : "=r"(lo) : "f"(x1 - h1), "f"(x0 - h0));
    hi = h;
}
__device__ __forceinline__ void mma_bf16(float c[4], const uint32_t a[4], const uint32_t b[2]) {
    asm volatile("mma.sync.aligned.m16n8k16.row.col.f32.bf16.bf16.f32 "
                 "{%0,%1,%2,%3}, {%4,%5,%6,%7}, {%8,%9}, {%0,%1,%2,%3};\n"
                 : "+f"(c[0]), "+f"(c[1]), "+f"(c[2]), "+f"(c[3])
                 : "r"(a[0]), "r"(a[1]), "r"(a[2]), "r"(a[3]),
                   "r"(b[0]), "r"(b[1]));
}
__device__ __forceinline__ uint32_t sptr(const void* p) {
    return (uint32_t)__cvta_generic_to_shared(p);
}
__device__ __forceinline__ void ldm_x4(uint32_t r[4], uint32_t addr) {
    asm volatile("ldmatrix.sync.aligned.m8n8.x4.shared.b16 {%0,%1,%2,%3}, [%4];"
                 : "=r"(r[0]), "=r"(r[1]), "=r"(r[2]), "=r"(r[3]) : "r"(addr));
}
#define ONES2 0x3F803F80u   // (1.0bf16, 1.0bf16)

__device__ __forceinline__ uint32_t aoff_lane(int lane, int stridew) {
    return ((lane & 15) * stridew + ((lane >> 4) << 2)) * 4;
}
__device__ __forceinline__ uint32_t boff_lane(int lane, int stridew) {
    return ((((lane >> 4) << 3) + (lane & 7)) * stridew + ((lane & 8) ? 4 : 0)) * 4;
}

// ===========================================================================
// 3xBF16 projection GEMM (unchanged from round 9)
// ===========================================================================
#define GSMBUF 4608
#define SMEM_GEMM_BYTES (2 * GSMBUF * 4)

__device__ __forceinline__ void bf16_body(const float* __restrict__ A,
                                          const float* __restrict__ B,
                                          float* __restrict__ C,
                                          int N, int K, int bm, int bn,
                                          uint32_t* sm) {
    const int tid  = threadIdx.x, lane = tid & 31, w = tid >> 5;
    const int wm = w >> 1, wn = w & 1;
    const int gid = lane >> 2, tig = lane & 3;
    const int ar = tid >> 1, aw0 = (tid & 1) * 4;
    const int bnn = tid & 63, bkq = tid >> 6;
    const uint32_t ao12 = aoff_lane(lane, 12);
    const uint32_t bo12 = boff_lane(lane, 12);

    float acc[2][4][4] = {};
    const int nit = K / 16;

    float4 av0 = *(const float4*)&A[(bm + ar) * K + aw0 * 2];
    float4 av1 = *(const float4*)&A[(bm + ar) * K + aw0 * 2 + 4];
    float bv0 = B[(bkq * 4 + 0) * N + bn + bnn];
    float bv1 = B[(bkq * 4 + 1) * N + bn + bnn];
    float bv2 = B[(bkq * 4 + 2) * N + bn + bnn];
    float bv3 = B[(bkq * 4 + 3) * N + bn + bnn];

    auto cvst = [&](uint32_t* buf, float4 A0, float4 A1,
                    float b0, float b1, float b2, float b3) {
        uint32_t* Ah = buf;
        uint32_t* Al = buf + 1536;
        uint32_t* Bh = buf + 3072;
        uint32_t* Bl = buf + 3840;
        uint32_t h, l;
        split_pack(A0.x, A0.y, h, l); Ah[ar*12 + aw0 + 0] = h; Al[ar*12 + aw0 + 0] = l;
        split_pack(A0.z, A0.w, h, l); Ah[ar*12 + aw0 + 1] = h; Al[ar*12 + aw0 + 1] = l;
        split_pack(A1.x, A1.y, h, l); Ah[ar*12 + aw0 + 2] = h; Al[ar*12 + aw0 + 2] = l;
        split_pack(A1.z, A1.w, h, l); Ah[ar*12 + aw0 + 3] = h; Al[ar*12 + aw0 + 3] = l;
        split_pack(b0, b1, h, l);     Bh[bnn*12 + bkq*2]   = h; Bl[bnn*12 + bkq*2]   = l;
        split_pack(b2, b3, h, l);     Bh[bnn*12 + bkq*2+1] = h; Bl[bnn*12 + bkq*2+1] = l;
    };

    cvst(sm, av0, av1, bv0, bv1, bv2, bv3);
    __syncthreads();

    for (int it = 0; it < nit; it++) {
        uint32_t* cb = sm + (it & 1) * GSMBUF;
        if (it + 1 < nit) {
            int k0 = (it + 1) * 16;
            av0 = *(const float4*)&A[(bm + ar) * K + k0 + aw0 * 2];
            av1 = *(const float4*)&A[(bm + ar) * K + k0 + aw0 * 2 + 4];
            bv0 = B[(k0 + bkq * 4 + 0) * N + bn + bnn];
            bv1 = B[(k0 + bkq * 4 + 1) * N + bn + bnn];
            bv2 = B[(k0 + bkq * 4 + 2) * N + bn + bnn];
            bv3 = B[(k0 + bkq * 4 + 3) * N + bn + bnn];
        }
        const uint32_t cbs = sptr(cb);
        uint32_t ah[2][4], al_[2][4], bh4[2][4], bl4[2][4];
#pragma unroll
        for (int mt = 0; mt < 2; mt++) {
            uint32_t rb = (uint32_t)(wm * 32 + mt * 16) * 48;
            ldm_x4(ah[mt],  cbs + rb + ao12);
            ldm_x4(al_[mt], cbs + 1536 * 4 + rb + ao12);
        }
#pragma unroll
        for (int p = 0; p < 2; p++) {
            uint32_t rb = (uint32_t)(wn * 32 + p * 16) * 48;
            ldm_x4(bh4[p], cbs + 3072 * 4 + rb + bo12);
            ldm_x4(bl4[p], cbs + 3840 * 4 + rb + bo12);
        }
#pragma unroll
        for (int mt = 0; mt < 2; mt++)
#pragma unroll
            for (int nt = 0; nt < 4; nt++) {
                const uint32_t* bh = bh4[nt >> 1] + (nt & 1) * 2;
                const uint32_t* bl = bl4[nt >> 1] + (nt & 1) * 2;
                mma_bf16(acc[mt][nt], ah[mt],  bh);
                mma_bf16(acc[mt][nt], ah[mt],  bl);
                mma_bf16(acc[mt][nt], al_[mt], bh);
            }
        if (it + 1 < nit) cvst(sm + ((it + 1) & 1) * GSMBUF, av0, av1, bv0, bv1, bv2, bv3);
        __syncthreads();
    }

#pragma unroll
    for (int mt = 0; mt < 2; mt++)
#pragma unroll
        for (int nt = 0; nt < 4; nt++) {
            int row = bm + wm * 32 + mt * 16 + gid;
            int col = bn + wn * 32 + nt * 8 + tig * 2;
            *(float2*)&C[row * N + col]       = make_float2(acc[mt][nt][0], acc[mt][nt][1]);
            *(float2*)&C[(row + 8) * N + col] = make_float2(acc[mt][nt][2], acc[mt][nt][3]);
        }
}

__global__ __launch_bounds__(256) void qkv_gemm(const float* __restrict__ hs,
                                                const float* __restrict__ Wq,
                                                const float* __restrict__ Wk,
                                                const float* __restrict__ Wv) {
    extern __shared__ uint32_t smext[];
    const int bx = blockIdx.x, bm = blockIdx.y * 128;
    const float* B; float* C; int N, bn;
    if (bx < 3)      { B = Wq; C = g_Q; N = NH * FD; bn = bx * 64; }
    else if (bx < 6) { B = Wk; C = g_K; N = NH * FD; bn = (bx - 3) * 64; }
    else             { B = Wv; C = g_V; N = DM;      bn = (bx - 6) * 64; }
    bf16_body(hs, B, C, N, DM, bm, bn, smext);
}

__global__ __launch_bounds__(256) void o_gemm(const float* __restrict__ Wo,
                                              float* __restrict__ out) {
    extern __shared__ uint32_t smext[];
    bf16_body(g_Y, Wo, out, DM, DM, blockIdx.y * 128, blockIdx.x * 64, smext);
}

// ===========================================================================
// Featurize + pack (unchanged from round 9).  grid (NC, NH, 4).
// ===========================================================================
__global__ __launch_bounds__(256) void featurize_k() {
    const int c = blockIdx.x, h = blockIdx.y, job = blockIdx.z;
    const int tid = threadIdx.x;

    if (job == 3) {   // V transpose + pack (stride 68: float4-aligned rows)
        __shared__ float vs[64][68];
#pragma unroll
        for (int l = 0; l < 4; l++) {
            int fi = tid + l * 256;
            int i = fi >> 4, d4 = (fi & 15) * 4;
            *(float4*)&vs[i][d4] = *(const float4*)&g_V[(c * CH + i) * DM + h * HD + d4];
        }
        __syncthreads();
        int vb = (h * NC + c) * V_WORDS;
#pragma unroll
        for (int l = 0; l < 8; l++) {
            int wd = tid + l * 256;
            int d = wd >> 5, iw = wd & 31;
            uint32_t hi, lo;
            split_pack(vs[2 * iw][d], vs[2 * iw + 1][d], hi, lo);
            g_Vh[vb + wd] = hi; g_Vl[vb + wd] = lo;
        }
        return;
    }

    __shared__ float xs[64][17];
    const float* __restrict__ src = (job == 0) ? g_Q : g_K;
    for (int idx = tid; idx < CH * FD; idx += 256) {
        int i = idx >> 4, f = idx & 15;
        xs[i][f] = src[(c * CH + i) * (NH * FD) + h * FD + f];
    }
    __syncthreads();
    const float S1 = 0.5f;
    const float S2 = 0.17677669529663687f;
    auto feat = [&](int i, int n) -> float {
        if (n == 0)  return 1.0f;
        if (n <= 16) return xs[i][n - 1] * S1;
        if (n <= 272) { int p = n - 17; return xs[i][p >> 4] * xs[i][p & 15] * S2; }
        return 0.0f;
    };
    const int base = (h * NC + c) * QK_WORDS;
    if (job <= 1) {
        uint32_t* dh = job ? g_K1h : g_Qh;
        uint32_t* dl = job ? g_K1l : g_Ql;
        int i = 0, nw = tid;
        if (nw >= NW) { nw -= NW; i++; }
#pragma unroll 4
        for (int l = 0; l < 36; l++) {
            uint32_t hi, lo;
            split_pack(feat(i, 2 * nw), feat(i, 2 * nw + 1), hi, lo);
            int wd = i * NW + nw;
            dh[base + wd] = hi; dl[base + wd] = lo;
            nw += 256;
            if (nw >= NW) { nw -= NW; i++; }
            if (nw >= NW) { nw -= NW; i++; }
        }
    } else {
#pragma unroll 4
        for (int l = 0; l < 36; l++) {
            int wd = tid + l * 256;
            int n = wd >> 5, iw = wd & 31;
            uint32_t hi, lo;
            split_pack(feat(2 * iw, n), feat(2 * iw + 1, n), hi, lo);
            g_K2h[base + wd] = hi; g_K2l[base + wd] = lo;
        }
    }
}

// ===========================================================================
// kv_scan: fused chunk-KV + exclusive prefix + bf16 pack.
// grid (18 feature-rowtiles of 16, NH), ONE warp per block.  The warp scans
// all 16 chunks: (a) writes the packed exclusive-prefix state (shfl pairs
// adjacent n rows across lanes), (b) mma-accumulates chunk c into fp32 regs.
// Eliminates g_S/g_ks roundtrip (28 MB) and the separate prefix kernel.
// ===========================================================================
__global__ __launch_bounds__(32) void kv_scan_k() {
    const int ntile = blockIdx.x, h = blockIdx.y;
    const int lane = threadIdx.x;
    const int gid = lane >> 2, tig = lane & 3;
    const int base = ntile * 16;
    float acc[8][4] = {}, acck[4] = {};
    const uint32_t ones[2] = { ONES2, ONES2 };
    const bool wr = ((gid & 1) == 0);
    const int nw0 = ntile * 8 + (gid >> 1);   // nw1 = nw0 + 4

    for (int c = 0; c < NC; c++) {
        const int qb = (h * NC + c) * QK_WORDS;
        // (a) write exclusive prefix, packed along n via lane^4 shuffle
#pragma unroll
        for (int nt = 0; nt < 8; nt++) {
            float p0 = __shfl_xor_sync(0xffffffffu, acc[nt][0], 4);
            float p1 = __shfl_xor_sync(0xffffffffu, acc[nt][1], 4);
            float p2 = __shfl_xor_sync(0xffffffffu, acc[nt][2], 4);
            float p3 = __shfl_xor_sync(0xffffffffu, acc[nt][3], 4);
            if (wr) {
                int d0 = nt * 8 + tig * 2;
                uint32_t hi, lo;
                split_pack(acc[nt][0], p0, hi, lo);
                g_Sh[qb + d0 * NW + nw0] = hi;       g_Sl[qb + d0 * NW + nw0] = lo;
                split_pack(acc[nt][1], p1, hi, lo);
                g_Sh[qb + (d0+1) * NW + nw0] = hi;   g_Sl[qb + (d0+1) * NW + nw0] = lo;
                split_pack(acc[nt][2], p2, hi, lo);
                g_Sh[qb + d0 * NW + nw0+4] = hi;     g_Sl[qb + d0 * NW + nw0+4] = lo;
                split_pack(acc[nt][3], p3, hi, lo);
                g_Sh[qb + (d0+1) * NW + nw0+4] = hi; g_Sl[qb + (d0+1) * NW + nw0+4] = lo;
            }
        }
        {
            float p0 = __shfl_xor_sync(0xffffffffu, acck[0], 4);
            float p2 = __shfl_xor_sync(0xffffffffu, acck[2], 4);
            if (wr && tig == 0) {
                uint32_t hi, lo;
                split_pack(acck[0], p0, hi, lo);
                g_kh[(h*NC+c) * NW + nw0] = hi;     g_kl[(h*NC+c) * NW + nw0] = lo;
                split_pack(acck[2], p2, hi, lo);
                g_kh[(h*NC+c) * NW + nw0+4] = hi;   g_kl[(h*NC+c) * NW + nw0+4] = lo;
            }
        }
        // (b) accumulate chunk c: S[n][d] += sum_i Kf[n][i] V[i][d]
        const int kb2 = (h * NC + c) * K2_WORDS;
        const int vb  = (h * NC + c) * V_WORDS;
#pragma unroll
        for (int ks = 0; ks < 4; ks++) {
            const int kw = ks * 8;
            const int r0 = kb2 + (base + gid) * 32 + kw + tig;
            const int r1 = kb2 + (base + gid + 8) * 32 + kw + tig;
            uint32_t ah[4], al_[4];
            ah[0] = g_K2h[r0]; ah[1] = g_K2h[r1]; ah[2] = g_K2h[r0 + 4]; ah[3] = g_K2h[r1 + 4];
            al_[0] = g_K2l[r0]; al_[1] = g_K2l[r1]; al_[2] = g_K2l[r0 + 4]; al_[3] = g_K2l[r1 + 4];
#pragma unroll
            for (int nt = 0; nt < 8; nt++) {
                const int vr = vb + (nt * 8 + gid) * 32 + kw + tig;
                uint32_t bh[2] = { g_Vh[vr], g_Vh[vr + 4] };
                uint32_t bl[2] = { g_Vl[vr], g_Vl[vr + 4] };
                mma_bf16(acc[nt], ah,  bh);
                mma_bf16(acc[nt], ah,  bl);
                mma_bf16(acc[nt], al_, bh);
            }
            mma_bf16(acck, ah,  ones);
            mma_bf16(acck, al_, ones);
        }
    }
}

// ===========================================================================
// chunk_attn: direct-global fragments, NO mainloop smem staging or syncs.
// per (c,h) block, 256 thr, 8 warps (wm 2 x wn 4).
// ===========================================================================
__global__ __launch_bounds__(256, 2) void chunk_attn_k() {
    __shared__ uint32_t Ash[2304];   // masked scores hi, [i][jw] stride 36
    __shared__ uint32_t Asl[2304];
    __shared__ float    den[64];

    const int c = blockIdx.x, h = blockIdx.y;
    const int tid = threadIdx.x, w = tid >> 5, lane = tid & 31;
    const int wm = w >> 2, wn = w & 3;
    const int gid = lane >> 2, tig = lane & 3;
    const uint32_t ao36 = aoff_lane(lane, 36);

    const int qb  = (h * NC + c) * QK_WORDS;
    const int ksb = (h * NC + c) * NW;
    const int vb  = (h * NC + c) * V_WORDS;

    float aA[2][2][4] = {}, aN[2][2][4] = {}, aD[2][4] = {};
    const uint32_t ones[2] = { ONES2, ONES2 };

#pragma unroll 2
    for (int s = 0; s < 18; s++) {
        const int kw = s * 8;
        uint32_t qh[2][4], ql[2][4];
#pragma unroll
        for (int mt = 0; mt < 2; mt++) {
            const int rb = wm * 32 + mt * 16;
            const int r0 = qb + (rb + gid) * NW + kw + tig;
            const int r1 = qb + (rb + gid + 8) * NW + kw + tig;
            qh[mt][0] = g_Qh[r0]; qh[mt][1] = g_Qh[r1];
            qh[mt][2] = g_Qh[r0 + 4]; qh[mt][3] = g_Qh[r1 + 4];
            ql[mt][0] = g_Ql[r0]; ql[mt][1] = g_Ql[r1];
            ql[mt][2] = g_Ql[r0 + 4]; ql[mt][3] = g_Ql[r1 + 4];
        }
        uint32_t kh[2][2], kl_[2][2], sh[2][2], sl_[2][2];
#pragma unroll
        for (int nt = 0; nt < 2; nt++) {
            const int rr = qb + (wn * 16 + nt * 8 + gid) * NW + kw + tig;
            kh[nt][0]  = g_K1h[rr]; kh[nt][1]  = g_K1h[rr + 4];
            kl_[nt][0] = g_K1l[rr]; kl_[nt][1] = g_K1l[rr + 4];
            sh[nt][0]  = g_Sh[rr];  sh[nt][1]  = g_Sh[rr + 4];
            sl_[nt][0] = g_Sl[rr];  sl_[nt][1] = g_Sl[rr + 4];
        }
#pragma unroll
        for (int mt = 0; mt < 2; mt++)
#pragma unroll
            for (int nt = 0; nt < 2; nt++) {
                mma_bf16(aA[mt][nt], qh[mt], kh[nt]);
                mma_bf16(aA[mt][nt], qh[mt], kl_[nt]);
                mma_bf16(aA[mt][nt], ql[mt], kh[nt]);
                mma_bf16(aN[mt][nt], qh[mt], sh[nt]);
                mma_bf16(aN[mt][nt], qh[mt], sl_[nt]);
                mma_bf16(aN[mt][nt], ql[mt], sh[nt]);
            }
        if (wn == 0) {
            uint32_t bh2[2] = { g_kh[ksb + kw + tig], g_kh[ksb + kw + tig + 4] };
            uint32_t bl2[2] = { g_kl[ksb + kw + tig], g_kl[ksb + kw + tig + 4] };
#pragma unroll
            for (int mt = 0; mt < 2; mt++) {
                mma_bf16(aD[mt], qh[mt], bh2);
                mma_bf16(aD[mt], qh[mt], bl2);
                mma_bf16(aD[mt], ql[mt], bh2);
            }
        }
    }

    // mask scores (keep j <= i), pack, stash to smem
#pragma unroll
    for (int mt = 0; mt < 2; mt++)
#pragma unroll
        for (int nt = 0; nt < 2; nt++) {
            int ri0 = wm * 32 + mt * 16 + gid, ri1 = ri0 + 8;
            int j0 = wn * 16 + nt * 8 + tig * 2;
            int jw = wn * 8 + nt * 4 + tig;
            float x0 = (j0     <= ri0) ? aA[mt][nt][0] : 0.f;
            float x1 = (j0 + 1 <= ri0) ? aA[mt][nt][1] : 0.f;
            float x2 = (j0     <= ri1) ? aA[mt][nt][2] : 0.f;
            float x3 = (j0 + 1 <= ri1) ? aA[mt][nt][3] : 0.f;
            uint32_t hi, lo;
            split_pack(x0, x1, hi, lo); Ash[ri0 * 36 + jw] = hi; Asl[ri0 * 36 + jw] = lo;
            split_pack(x2, x3, hi, lo); Ash[ri1 * 36 + jw] = hi; Asl[ri1 * 36 + jw] = lo;
        }
    __syncthreads();

    // phase 2: num += A @ V ; den += rowsum(A)
    const uint32_t ashs = sptr(Ash), asls = sptr(Asl);
#pragma unroll
    for (int ks = 0; ks < 4; ks++) {
        const int kw = ks * 8;
        uint32_t ah[2][4], al2[2][4];
#pragma unroll
        for (int mt = 0; mt < 2; mt++) {
            uint32_t rb = (uint32_t)(wm * 32 + mt * 16) * 144 + kw * 4;
            ldm_x4(ah[mt],  ashs + rb + ao36);
            ldm_x4(al2[mt], asls + rb + ao36);
        }
#pragma unroll
        for (int nt = 0; nt < 2; nt++) {
            const int d = wn * 16 + nt * 8 + gid;
            uint32_t bh2[2] = { g_Vh[vb + d*32 + kw + tig], g_Vh[vb + d*32 + kw + tig + 4] };
            uint32_t bl2[2] = { g_Vl[vb + d*32 + kw + tig], g_Vl[vb + d*32 + kw + tig + 4] };
#pragma unroll
            for (int mt = 0; mt < 2; mt++) {
                mma_bf16(aN[mt][nt], ah[mt],  bh2);
                mma_bf16(aN[mt][nt], ah[mt],  bl2);
                mma_bf16(aN[mt][nt], al2[mt], bh2);
            }
        }
        if (wn == 0) {
#pragma unroll
            for (int mt = 0; mt < 2; mt++) {
                mma_bf16(aD[mt], ah[mt],  ones);
                mma_bf16(aD[mt], al2[mt], ones);
            }
        }
    }
    if (wn == 0 && tig == 0) {
#pragma unroll
        for (int mt = 0; mt < 2; mt++) {
            den[wm * 32 + mt * 16 + gid]     = aD[mt][0];
            den[wm * 32 + mt * 16 + gid + 8] = aD[mt][2];
        }
    }
    __syncthreads();

    // divide & store
#pragma unroll
    for (int mt = 0; mt < 2; mt++) {
        int ri0 = wm * 32 + mt * 16 + gid, ri1 = ri0 + 8;
        float inv0 = 1.0f / (den[ri0] + 1e-12f);
        float inv1 = 1.0f / (den[ri1] + 1e-12f);
#pragma unroll
        for (int nt = 0; nt < 2; nt++) {
            int cb0 = wn * 16 + nt * 8 + tig * 2;
            *(float2*)&g_Y[(c * CH + ri0) * DM + h * HD + cb0] =
                make_float2(aN[mt][nt][0] * inv0, aN[mt][nt][1] * inv0);
            *(float2*)&g_Y[(c * CH + ri1) * DM + h * HD + cb0] =
                make_float2(aN[mt][nt][2] * inv1, aN[mt][nt][3] * inv1);
        }
    }
}

// ---------------------------------------------------------------------------
extern "C" void kernel_launch(void* const* d_in, const int* in_sizes, int n_in,
                              void* d_out, int out_size) {
    const float* hs = (const float*)d_in[0];
    const float* Wq = (const float*)d_in[1];
    const float* Wk = (const float*)d_in[2];
    const float* Wv = (const float*)d_in[3];
    const float* Wo = (const float*)d_in[4];
    float* out = (float*)d_out;

    cudaFuncSetAttribute(qkv_gemm, cudaFuncAttributeMaxDynamicSharedMemorySize, SMEM_GEMM_BYTES);
    cudaFuncSetAttribute(o_gemm,   cudaFuncAttributeMaxDynamicSharedMemorySize, SMEM_GEMM_BYTES);

    dim3 thr(256);
    qkv_gemm<<<dim3(18, 8), thr, SMEM_GEMM_BYTES>>>(hs, Wq, Wk, Wv);
    featurize_k<<<dim3(NC, NH, 4), thr>>>();
    kv_scan_k<<<dim3(18, NH), 32>>>();
    chunk_attn_k<<<dim3(NC, NH), thr>>>();
    o_gemm<<<dim3(12, 8), thr, SMEM_GEMM_BYTES>>>(Wo, out);
}

// round 12
// speedup vs baseline: 1.5729x; 1.5729x over previous
#include <cuda_runtime.h>
#include <cstdint>

// Problem constants
#define LL 1024
#define DM 768
#define NH 12
#define FD 16
#define HD 64
#define CH 64
#define NC 16
#define DP 288           // padded expanded feature dim (273 -> 288)
#define NW 144           // DP/2 packed words
#define QK_WORDS (64*NW) // 9216 words per (h,c): [row64][nw144]
#define K2_WORDS (DP*32) // 9216 words per (h,c): [n288][iw32]
#define V_WORDS  (64*32) // 2048 words per (h,c): [d64][iw32]
#define S_ELT    (64*DP) // 18432 fp32 per (h,c), layout [d][n]

// Scratch (static device globals)
__device__ float    g_Q[LL*NH*FD];
__device__ float    g_K[LL*NH*FD];
__device__ float    g_V[LL*DM];
__device__ uint32_t g_Qh [NH*NC*QK_WORDS], g_Ql [NH*NC*QK_WORDS]; // Qf packed along n
__device__ uint32_t g_K1h[NH*NC*QK_WORDS], g_K1l[NH*NC*QK_WORDS]; // Kf packed along n (attn B)
__device__ uint32_t g_K2h[NH*NC*K2_WORDS], g_K2l[NH*NC*K2_WORDS]; // Kf packed along i (kv A)
__device__ uint32_t g_Vh [NH*NC*V_WORDS],  g_Vl [NH*NC*V_WORDS];  // V packed along token
__device__ float    g_S  [NH*NC*S_ELT];   // per-chunk KV sums, [d][n]
__device__ float    g_ks [NH*NC*DP];      // per-chunk k-feature sums
__device__ uint32_t g_Sh [NH*NC*QK_WORDS], g_Sl [NH*NC*QK_WORDS]; // prefix S packed: [d][nw]
__device__ uint32_t g_kh [NH*NC*NW],       g_kl [NH*NC*NW];       // prefix ksum packed
__device__ float    g_Y[LL*DM];

// ---------------------------------------------------------------------------
// bf16 split-pack helpers.  x = hi + lo with hi,lo bf16; dropped lo*lo ~2^-18.
// ---------------------------------------------------------------------------
__device__ __forceinline__ void split_pack(float x0, float x1, uint32_t& hi, uint32_t& lo) {
    uint32_t h;
    asm("cvt.rn.bf16x2.f32 %0, %1, %2;" : "=r"(h) : "f"(x1), "f"(x0));  // hi: x1->upper, x0->lower
    float h0 = __uint_as_float(h << 16);
    float h1 = __uint_as_float(h & 0xffff0000u);
    asm("cvt.rn.bf16x2.f32 %0, %1, %2;" : "=r"(lo) : "f"(x1 - h1), "f"(x0 - h0));
    hi = h;
}
__device__ __forceinline__ void mma_bf16(float c[4], const uint32_t a[4], const uint32_t b[2]) {
    asm volatile("mma.sync.aligned.m16n8k16.row.col.f32.bf16.bf16.f32 "
                 "{%0,%1,%2,%3}, {%4,%5,%6,%7}, {%8,%9}, {%0,%1,%2,%3};\n"
                 : "+f"(c[0]), "+f"(c[1]), "+f"(c[2]), "+f"(c[3])
                 : "r"(a[0]), "r"(a[1]), "r"(a[2]), "r"(a[3]),
                   "r"(b[0]), "r"(b[1]));
}
#define ONES2 0x3F803F80u   // (1.0bf16, 1.0bf16)

// ===========================================================================
// 3xBF16 projection GEMM: C[1024 x N] = A[1024 x K] @ B[K x N].
// Block 128x64, 256 thr = 8 warps (4x2), warp 32x32 = 2x4 m16n8k16 tiles.
// Packed bf16x2 smem (stride 12 words: conflict-free fragment LDS),
// double-buffered with register prefetch.  24 mma per K16 stage.
// (round-8 proven configuration: scalar LDS fragments, NOT ldmatrix)
// ===========================================================================
#define GSMBUF 4608                       // words per buffer
#define SMEM_GEMM_BYTES (2 * GSMBUF * 4)  // 36864 B

__device__ __forceinline__ void bf16_body(const float* __restrict__ A,
                                          const float* __restrict__ B,
                                          float* __restrict__ C,
                                          int N, int K, int bm, int bn,
                                          uint32_t* sm) {
    const int tid  = threadIdx.x, lane = tid & 31, w = tid >> 5;
    const int wm = w >> 1, wn = w & 1;
    const int gid = lane >> 2, tig = lane & 3;
    const int ar = tid >> 1, aw0 = (tid & 1) * 4;   // A staging: row ar, words aw0..aw0+3
    const int bnn = tid & 63, bkq = tid >> 6;       // B staging: row bnn, words bkq*2..+1

    float acc[2][4][4] = {};
    const int nit = K / 16;

    float4 av0 = *(const float4*)&A[(bm + ar) * K + aw0 * 2];
    float4 av1 = *(const float4*)&A[(bm + ar) * K + aw0 * 2 + 4];
    float bv0 = B[(bkq * 4 + 0) * N + bn + bnn];
    float bv1 = B[(bkq * 4 + 1) * N + bn + bnn];
    float bv2 = B[(bkq * 4 + 2) * N + bn + bnn];
    float bv3 = B[(bkq * 4 + 3) * N + bn + bnn];

    auto cvst = [&](uint32_t* buf, float4 A0, float4 A1,
                    float b0, float b1, float b2, float b3) {
        uint32_t* Ah = buf;
        uint32_t* Al = buf + 1536;
        uint32_t* Bh = buf + 3072;
        uint32_t* Bl = buf + 3840;
        uint32_t h, l;
        split_pack(A0.x, A0.y, h, l); Ah[ar*12 + aw0 + 0] = h; Al[ar*12 + aw0 + 0] = l;
        split_pack(A0.z, A0.w, h, l); Ah[ar*12 + aw0 + 1] = h; Al[ar*12 + aw0 + 1] = l;
        split_pack(A1.x, A1.y, h, l); Ah[ar*12 + aw0 + 2] = h; Al[ar*12 + aw0 + 2] = l;
        split_pack(A1.z, A1.w, h, l); Ah[ar*12 + aw0 + 3] = h; Al[ar*12 + aw0 + 3] = l;
        split_pack(b0, b1, h, l);     Bh[bnn*12 + bkq*2]   = h; Bl[bnn*12 + bkq*2]   = l;
        split_pack(b2, b3, h, l);     Bh[bnn*12 + bkq*2+1] = h; Bl[bnn*12 + bkq*2+1] = l;
    };

    cvst(sm, av0, av1, bv0, bv1, bv2, bv3);
    __syncthreads();

    for (int it = 0; it < nit; it++) {
        uint32_t* cb = sm + (it & 1) * GSMBUF;
        if (it + 1 < nit) {
            int k0 = (it + 1) * 16;
            av0 = *(const float4*)&A[(bm + ar) * K + k0 + aw0 * 2];
            av1 = *(const float4*)&A[(bm + ar) * K + k0 + aw0 * 2 + 4];
            bv0 = B[(k0 + bkq * 4 + 0) * N + bn + bnn];
            bv1 = B[(k0 + bkq * 4 + 1) * N + bn + bnn];
            bv2 = B[(k0 + bkq * 4 + 2) * N + bn + bnn];
            bv3 = B[(k0 + bkq * 4 + 3) * N + bn + bnn];
        }
        uint32_t* Ah = cb;
        uint32_t* Al = cb + 1536;
        uint32_t* Bh = cb + 3072;
        uint32_t* Bl = cb + 3840;
        uint32_t ah[2][4], al_[2][4], bh[4][2], bl_[4][2];
#pragma unroll
        for (int mt = 0; mt < 2; mt++) {
            int rb = wm * 32 + mt * 16;
            ah[mt][0] = Ah[(rb+gid)*12 + tig];     ah[mt][1] = Ah[(rb+gid+8)*12 + tig];
            ah[mt][2] = Ah[(rb+gid)*12 + tig+4];   ah[mt][3] = Ah[(rb+gid+8)*12 + tig+4];
            al_[mt][0] = Al[(rb+gid)*12 + tig];    al_[mt][1] = Al[(rb+gid+8)*12 + tig];
            al_[mt][2] = Al[(rb+gid)*12 + tig+4];  al_[mt][3] = Al[(rb+gid+8)*12 + tig+4];
        }
#pragma unroll
        for (int nt = 0; nt < 4; nt++) {
            int nb = wn * 32 + nt * 8;
            bh[nt][0] = Bh[(nb+gid)*12 + tig];   bh[nt][1] = Bh[(nb+gid)*12 + tig+4];
            bl_[nt][0] = Bl[(nb+gid)*12 + tig];  bl_[nt][1] = Bl[(nb+gid)*12 + tig+4];
        }
#pragma unroll
        for (int mt = 0; mt < 2; mt++)
#pragma unroll
            for (int nt = 0; nt < 4; nt++) {
                mma_bf16(acc[mt][nt], ah[mt],  bh[nt]);
                mma_bf16(acc[mt][nt], ah[mt],  bl_[nt]);
                mma_bf16(acc[mt][nt], al_[mt], bh[nt]);
            }
        if (it + 1 < nit) cvst(sm + ((it + 1) & 1) * GSMBUF, av0, av1, bv0, bv1, bv2, bv3);
        __syncthreads();
    }

#pragma unroll
    for (int mt = 0; mt < 2; mt++)
#pragma unroll
        for (int nt = 0; nt < 4; nt++) {
            int row = bm + wm * 32 + mt * 16 + gid;
            int col = bn + wn * 32 + nt * 8 + tig * 2;
            *(float2*)&C[row * N + col]       = make_float2(acc[mt][nt][0], acc[mt][nt][1]);
            *(float2*)&C[(row + 8) * N + col] = make_float2(acc[mt][nt][2], acc[mt][nt][3]);
        }
}

__global__ __launch_bounds__(256) void qkv_gemm(const float* __restrict__ hs,
                                                const float* __restrict__ Wq,
                                                const float* __restrict__ Wk,
                                                const float* __restrict__ Wv) {
    extern __shared__ uint32_t smext[];
    const int bx = blockIdx.x, bm = blockIdx.y * 128;
    const float* B; float* C; int N, bn;
    if (bx < 3)      { B = Wq; C = g_Q; N = NH * FD; bn = bx * 64; }
    else if (bx < 6) { B = Wk; C = g_K; N = NH * FD; bn = (bx - 3) * 64; }
    else             { B = Wv; C = g_V; N = DM;      bn = (bx - 6) * 64; }
    bf16_body(hs, B, C, N, DM, bm, bn, smext);
}

__global__ __launch_bounds__(256) void o_gemm(const float* __restrict__ Wo,
                                              float* __restrict__ out) {
    extern __shared__ uint32_t smext[];
    bf16_body(g_Y, Wo, out, DM, DM, blockIdx.y * 128, blockIdx.x * 64, smext);
}

// ===========================================================================
// Featurize + pack.  grid (NC, NH, 4):
//   z=0: Q  -> g_Qh/l  [i][nw]     z=1: K -> g_K1h/l [j][nw]
//   z=2: K  -> g_K2h/l [n][iw]     z=3: V -> g_Vh/l  [d][iw]
// ===========================================================================
__global__ __launch_bounds__(256) void featurize_k() {
    const int c = blockIdx.x, h = blockIdx.y, job = blockIdx.z;
    const int tid = threadIdx.x;

    if (job == 3) {   // V transpose + pack (stride 68: float4-aligned rows)
        __shared__ float vs[64][68];
#pragma unroll
        for (int l = 0; l < 4; l++) {
            int fi = tid + l * 256;
            int i = fi >> 4, d4 = (fi & 15) * 4;
            *(float4*)&vs[i][d4] = *(const float4*)&g_V[(c * CH + i) * DM + h * HD + d4];
        }
        __syncthreads();
        int vb = (h * NC + c) * V_WORDS;
#pragma unroll
        for (int l = 0; l < 8; l++) {
            int wd = tid + l * 256;
            int d = wd >> 5, iw = wd & 31;
            uint32_t hi, lo;
            split_pack(vs[2 * iw][d], vs[2 * iw + 1][d], hi, lo);
            g_Vh[vb + wd] = hi; g_Vl[vb + wd] = lo;
        }
        return;
    }

    __shared__ float xs[64][17];
    const float* __restrict__ src = (job == 0) ? g_Q : g_K;
    for (int idx = tid; idx < CH * FD; idx += 256) {
        int i = idx >> 4, f = idx & 15;
        xs[i][f] = src[(c * CH + i) * (NH * FD) + h * FD + f];
    }
    __syncthreads();
    const float S1 = 0.5f;
    const float S2 = 0.17677669529663687f;
    auto feat = [&](int i, int n) -> float {
        if (n == 0)  return 1.0f;
        if (n <= 16) return xs[i][n - 1] * S1;
        if (n <= 272) { int p = n - 17; return xs[i][p >> 4] * xs[i][p & 15] * S2; }
        return 0.0f;
    };
    const int base = (h * NC + c) * QK_WORDS;
    if (job <= 1) {      // [row i][nw]; incremental i/nw (no div by 144)
        uint32_t* dh = job ? g_K1h : g_Qh;
        uint32_t* dl = job ? g_K1l : g_Ql;
        int i = 0, nw = tid;
        if (nw >= NW) { nw -= NW; i++; }
#pragma unroll 4
        for (int l = 0; l < 36; l++) {
            uint32_t hi, lo;
            split_pack(feat(i, 2 * nw), feat(i, 2 * nw + 1), hi, lo);
            int wd = i * NW + nw;
            dh[base + wd] = hi; dl[base + wd] = lo;
            nw += 256;
            if (nw >= NW) { nw -= NW; i++; }
            if (nw >= NW) { nw -= NW; i++; }
        }
    } else {             // job==2: [n][iw] packed along tokens
#pragma unroll 4
        for (int l = 0; l < 36; l++) {
            int wd = tid + l * 256;
            int n = wd >> 5, iw = wd & 31;
            uint32_t hi, lo;
            split_pack(feat(2 * iw, n), feat(2 * iw + 1, n), hi, lo);
            g_K2h[base + wd] = hi; g_K2l[base + wd] = lo;
        }
    }
}

// ===========================================================================
// chunk_kv (bf16 mma, smem-free): S[d][n] = sum_i Kf[n][i]*V[i][d],
// ksum[n] via ones-B.  grid (2 halves of 144 rows, NC, NH), 288 thr (9 warps).
// ===========================================================================
__global__ __launch_bounds__(288) void chunk_kv_k() {
    const int half = blockIdx.x, c = blockIdx.y, h = blockIdx.z;
    const int tid = threadIdx.x, w = tid >> 5, lane = tid & 31;
    const int gid = lane >> 2, tig = lane & 3;
    const int rbl = half * 144 + w * 16;
    const int kb2 = (h * NC + c) * K2_WORDS;
    const int vb  = (h * NC + c) * V_WORDS;
    float acc[8][4] = {}, acck[4] = {};
    const uint32_t ones[2] = { ONES2, ONES2 };

#pragma unroll
    for (int ks = 0; ks < 4; ks++) {
        const int kw = ks * 8;
        uint32_t ah[4], al_[4];
        ah[0]  = g_K2h[kb2 + (rbl+gid)*32   + kw + tig];
        ah[1]  = g_K2h[kb2 + (rbl+gid+8)*32 + kw + tig];
        ah[2]  = g_K2h[kb2 + (rbl+gid)*32   + kw + tig + 4];
        ah[3]  = g_K2h[kb2 + (rbl+gid+8)*32 + kw + tig + 4];
        al_[0] = g_K2l[kb2 + (rbl+gid)*32   + kw + tig];
        al_[1] = g_K2l[kb2 + (rbl+gid+8)*32 + kw + tig];
        al_[2] = g_K2l[kb2 + (rbl+gid)*32   + kw + tig + 4];
        al_[3] = g_K2l[kb2 + (rbl+gid+8)*32 + kw + tig + 4];
#pragma unroll
        for (int nt = 0; nt < 8; nt++) {
            uint32_t bh[2], bl_[2];
            bh[0]  = g_Vh[vb + (nt*8+gid)*32 + kw + tig];
            bh[1]  = g_Vh[vb + (nt*8+gid)*32 + kw + tig + 4];
            bl_[0] = g_Vl[vb + (nt*8+gid)*32 + kw + tig];
            bl_[1] = g_Vl[vb + (nt*8+gid)*32 + kw + tig + 4];
            mma_bf16(acc[nt], ah,  bh);
            mma_bf16(acc[nt], ah,  bl_);
            mma_bf16(acc[nt], al_, bh);
        }
        mma_bf16(acck, ah,  ones);
        mma_bf16(acck, al_, ones);
    }

    const int sb = (h * NC + c) * S_ELT;
    const int n0 = rbl + gid, n1 = n0 + 8;
#pragma unroll
    for (int nt = 0; nt < 8; nt++) {
        int d0 = nt * 8 + tig * 2;
        g_S[sb + d0 * DP + n0]       = acc[nt][0];
        g_S[sb + (d0 + 1) * DP + n0] = acc[nt][1];
        g_S[sb + d0 * DP + n1]       = acc[nt][2];
        g_S[sb + (d0 + 1) * DP + n1] = acc[nt][3];
    }
    if (tig == 0) {
        g_ks[(h * NC + c) * DP + n0] = acck[0];
        g_ks[(h * NC + c) * DP + n1] = acck[2];
    }
}

// ===========================================================================
// Exclusive prefix over chunks + bf16 pack.  MLP=16: prefetch all chunk
// values into registers (independent loads), then scan + pack + store.
// (measured 7.5us vs 12.3us serial)
// ===========================================================================
__global__ __launch_bounds__(256) void prefix_k() {
    const int gid = blockIdx.x * 256 + threadIdx.x;
    const int NSEG = NH * 64 * NW;   // 110592
    if (gid < NSEG) {
        int h = gid / (64 * NW), rem = gid % (64 * NW);
        int d = rem / NW, nw = rem % NW;
        const float* src = g_S + h * NC * S_ELT + d * DP + 2 * nw;
        uint32_t* dh = g_Sh + h * NC * QK_WORDS + d * NW + nw;
        uint32_t* dl = g_Sl + h * NC * QK_WORDS + d * NW + nw;
        float2 v[NC];
#pragma unroll
        for (int c = 0; c < NC; c++) v[c] = *(const float2*)&src[c * S_ELT];
        float a0 = 0.f, a1 = 0.f;
#pragma unroll
        for (int c = 0; c < NC; c++) {
            uint32_t hi, lo;
            split_pack(a0, a1, hi, lo);
            dh[c * QK_WORDS] = hi; dl[c * QK_WORDS] = lo;
            a0 += v[c].x; a1 += v[c].y;
        }
    } else if (gid < NSEG + NH * NW) {
        int j = gid - NSEG;
        int h = j / NW, nw = j % NW;
        const float* src = g_ks + h * NC * DP + 2 * nw;
        uint32_t* dh = g_kh + h * NC * NW + nw;
        uint32_t* dl = g_kl + h * NC * NW + nw;
        float v0[NC], v1[NC];
#pragma unroll
        for (int c = 0; c < NC; c++) { v0[c] = src[c * DP]; v1[c] = src[c * DP + 1]; }
        float a0 = 0.f, a1 = 0.f;
#pragma unroll
        for (int c = 0; c < NC; c++) {
            uint32_t hi, lo;
            split_pack(a0, a1, hi, lo);
            dh[c * NW] = hi; dl[c * NW] = lo;
            a0 += v0[c]; a1 += v1[c];
        }
    }
}

// ===========================================================================
// chunk_attn (bf16, staged smem pipeline, scalar LDS fragments — the proven
// round-8 configuration): per (c,h) block, 256 thr, 8 warps (wm 2 x wn 4).
// Mainloop 18 k16 stages: A += Q K^T, num += Q Sprev, den += Q ksum.
// Mask+pack scores -> smem, phase2: num += A@V, den += rowsum(A).
// ===========================================================================
#define ATTN_BUF 4624   // words: Qh 768 Ql 768 Kh 768 Kl 768 Sh 768 Sl 768 ksh 8 ksl 8
#define ATTN_SMEM ((2 * ATTN_BUF + 2 * 2304 + 64) * 4)   // 55680 B
__global__ __launch_bounds__(256, 2) void chunk_attn_k() {
    extern __shared__ uint32_t usm[];
    uint32_t* bufs = usm;                    // 2 x ATTN_BUF
    uint32_t* Ash  = usm + 2 * ATTN_BUF;     // [i][jw] stride 36
    uint32_t* Asl  = Ash + 2304;
    float*    den  = (float*)(Asl + 2304);   // [64]

    const int c = blockIdx.x, h = blockIdx.y;
    const int tid = threadIdx.x, w = tid >> 5, lane = tid & 31;
    const int wm = w >> 2, wn = w & 3;
    const int gid = lane >> 2, tig = lane & 3;

    const int qb  = (h * NC + c) * QK_WORDS;
    const int ksb = (h * NC + c) * NW;
    const int vb  = (h * NC + c) * V_WORDS;

    const uint32_t* gsrc[6] = { g_Qh + qb, g_Ql + qb, g_K1h + qb,
                                g_K1l + qb, g_Sh + qb, g_Sl + qb };
    const int sr = tid >> 3, skw = tid & 7;     // staging coords

    // stage slice 0
    {
#pragma unroll
        for (int o = 0; o < 6; o++)
#pragma unroll
            for (int hf = 0; hf < 2; hf++) {
                int r = sr + hf * 32;
                bufs[o * 768 + r * 12 + skw] = gsrc[o][r * NW + skw];
            }
        if (tid < 8)       bufs[4608 + tid]     = g_kh[ksb + tid];
        else if (tid < 16) bufs[4616 + tid - 8] = g_kl[ksb + tid - 8];
    }
    __syncthreads();

    float aA[2][2][4] = {}, aN[2][2][4] = {}, aD[2][4] = {};
    const uint32_t ones[2] = { ONES2, ONES2 };

    for (int s = 0; s < 18; s++) {
        uint32_t* cb = bufs + (s & 1) * ATTN_BUF;
        uint32_t pf[12]; uint32_t pks = 0;
        if (s + 1 < 18) {
            const int kw0 = (s + 1) * 8;
#pragma unroll
            for (int o = 0; o < 6; o++)
#pragma unroll
                for (int hf = 0; hf < 2; hf++) {
                    int r = sr + hf * 32;
                    pf[o * 2 + hf] = gsrc[o][r * NW + kw0 + skw];
                }
            if (tid < 8)       pks = g_kh[ksb + kw0 + tid];
            else if (tid < 16) pks = g_kl[ksb + kw0 + tid - 8];
        }
        // fragments (scalar LDS, conflict-free via stride 12)
        uint32_t qh[2][4], ql[2][4];
#pragma unroll
        for (int mt = 0; mt < 2; mt++) {
            int rb = wm * 32 + mt * 16;
            qh[mt][0] = cb[(rb+gid)*12 + tig];         qh[mt][1] = cb[(rb+gid+8)*12 + tig];
            qh[mt][2] = cb[(rb+gid)*12 + tig+4];       qh[mt][3] = cb[(rb+gid+8)*12 + tig+4];
            ql[mt][0] = cb[768 + (rb+gid)*12 + tig];   ql[mt][1] = cb[768 + (rb+gid+8)*12 + tig];
            ql[mt][2] = cb[768 + (rb+gid)*12 + tig+4]; ql[mt][3] = cb[768 + (rb+gid+8)*12 + tig+4];
        }
        uint32_t kh[2][2], kl_[2][2], sh[2][2], sl_[2][2];
#pragma unroll
        for (int nt = 0; nt < 2; nt++) {
            int cbn = wn * 16 + nt * 8;
            kh[nt][0]  = cb[1536 + (cbn+gid)*12 + tig]; kh[nt][1]  = cb[1536 + (cbn+gid)*12 + tig+4];
            kl_[nt][0] = cb[2304 + (cbn+gid)*12 + tig]; kl_[nt][1] = cb[2304 + (cbn+gid)*12 + tig+4];
            sh[nt][0]  = cb[3072 + (cbn+gid)*12 + tig]; sh[nt][1]  = cb[3072 + (cbn+gid)*12 + tig+4];
            sl_[nt][0] = cb[3840 + (cbn+gid)*12 + tig]; sl_[nt][1] = cb[3840 + (cbn+gid)*12 + tig+4];
        }
#pragma unroll
        for (int mt = 0; mt < 2; mt++)
#pragma unroll
            for (int nt = 0; nt < 2; nt++) {
                mma_bf16(aA[mt][nt], qh[mt], kh[nt]);
                mma_bf16(aA[mt][nt], qh[mt], kl_[nt]);
                mma_bf16(aA[mt][nt], ql[mt], kh[nt]);
                mma_bf16(aN[mt][nt], qh[mt], sh[nt]);
                mma_bf16(aN[mt][nt], qh[mt], sl_[nt]);
                mma_bf16(aN[mt][nt], ql[mt], sh[nt]);
            }
        if (wn == 0) {
            uint32_t bh2[2] = { cb[4608 + tig], cb[4608 + tig + 4] };
            uint32_t bl2[2] = { cb[4616 + tig], cb[4616 + tig + 4] };
#pragma unroll
            for (int mt = 0; mt < 2; mt++) {
                mma_bf16(aD[mt], qh[mt], bh2);
                mma_bf16(aD[mt], qh[mt], bl2);
                mma_bf16(aD[mt], ql[mt], bh2);
            }
        }
        if (s + 1 < 18) {
            uint32_t* nb2 = bufs + ((s + 1) & 1) * ATTN_BUF;
#pragma unroll
            for (int o = 0; o < 6; o++)
#pragma unroll
                for (int hf = 0; hf < 2; hf++) {
                    int r = sr + hf * 32;
                    nb2[o * 768 + r * 12 + skw] = pf[o * 2 + hf];
                }
            if (tid < 8)       nb2[4608 + tid]     = pks;
            else if (tid < 16) nb2[4616 + tid - 8] = pks;
        }
        __syncthreads();
    }

    // mask scores (keep j <= i), pack, stash to smem
#pragma unroll
    for (int mt = 0; mt < 2; mt++)
#pragma unroll
        for (int nt = 0; nt < 2; nt++) {
            int ri0 = wm * 32 + mt * 16 + gid, ri1 = ri0 + 8;
            int j0 = wn * 16 + nt * 8 + tig * 2;
            int jw = wn * 8 + nt * 4 + tig;
            float x0 = (j0     <= ri0) ? aA[mt][nt][0] : 0.f;
            float x1 = (j0 + 1 <= ri0) ? aA[mt][nt][1] : 0.f;
            float x2 = (j0     <= ri1) ? aA[mt][nt][2] : 0.f;
            float x3 = (j0 + 1 <= ri1) ? aA[mt][nt][3] : 0.f;
            uint32_t hi, lo;
            split_pack(x0, x1, hi, lo); Ash[ri0 * 36 + jw] = hi; Asl[ri0 * 36 + jw] = lo;
            split_pack(x2, x3, hi, lo); Ash[ri1 * 36 + jw] = hi; Asl[ri1 * 36 + jw] = lo;
        }
    __syncthreads();

    // phase 2: num += A @ V ; den += rowsum(A)
#pragma unroll
    for (int ks = 0; ks < 4; ks++) {
        const int kw = ks * 8;
        uint32_t ah[2][4], al2[2][4];
#pragma unroll
        for (int mt = 0; mt < 2; mt++) {
            int rb = wm * 32 + mt * 16;
            ah[mt][0]  = Ash[(rb+gid)*36 + kw + tig];   ah[mt][1]  = Ash[(rb+gid+8)*36 + kw + tig];
            ah[mt][2]  = Ash[(rb+gid)*36 + kw + tig+4]; ah[mt][3]  = Ash[(rb+gid+8)*36 + kw + tig+4];
            al2[mt][0] = Asl[(rb+gid)*36 + kw + tig];   al2[mt][1] = Asl[(rb+gid+8)*36 + kw + tig];
            al2[mt][2] = Asl[(rb+gid)*36 + kw + tig+4]; al2[mt][3] = Asl[(rb+gid+8)*36 + kw + tig+4];
        }
#pragma unroll
        for (int nt = 0; nt < 2; nt++) {
            int d = wn * 16 + nt * 8 + gid;
            uint32_t bh2[2] = { g_Vh[vb + d*32 + kw + tig], g_Vh[vb + d*32 + kw + tig + 4] };
            uint32_t bl2[2] = { g_Vl[vb + d*32 + kw + tig], g_Vl[vb + d*32 + kw + tig + 4] };
#pragma unroll
            for (int mt = 0; mt < 2; mt++) {
                mma_bf16(aN[mt][nt], ah[mt],  bh2);
                mma_bf16(aN[mt][nt], ah[mt],  bl2);
                mma_bf16(aN[mt][nt], al2[mt], bh2);
            }
        }
        if (wn == 0) {
#pragma unroll
            for (int mt = 0; mt < 2; mt++) {
                mma_bf16(aD[mt], ah[mt],  ones);
                mma_bf16(aD[mt], al2[mt], ones);
            }
        }
    }
    if (wn == 0 && tig == 0) {
#pragma unroll
        for (int mt = 0; mt < 2; mt++) {
            den[wm * 32 + mt * 16 + gid]     = aD[mt][0];
            den[wm * 32 + mt * 16 + gid + 8] = aD[mt][2];
        }
    }
    __syncthreads();

    // divide & store
#pragma unroll
    for (int mt = 0; mt < 2; mt++) {
        int ri0 = wm * 32 + mt * 16 + gid, ri1 = ri0 + 8;
        float inv0 = 1.0f / (den[ri0] + 1e-12f);
        float inv1 = 1.0f / (den[ri1] + 1e-12f);
#pragma unroll
        for (int nt = 0; nt < 2; nt++) {
            int cb0 = wn * 16 + nt * 8 + tig * 2;
            *(float2*)&g_Y[(c * CH + ri0) * DM + h * HD + cb0] =
                make_float2(aN[mt][nt][0] * inv0, aN[mt][nt][1] * inv0);
            *(float2*)&g_Y[(c * CH + ri1) * DM + h * HD + cb0] =
                make_float2(aN[mt][nt][2] * inv1, aN[mt][nt][3] * inv1);
        }
    }
}

// ---------------------------------------------------------------------------
extern "C" void kernel_launch(void* const* d_in, const int* in_sizes, int n_in,
                              void* d_out, int out_size) {
    const float* hs = (const float*)d_in[0];
    const float* Wq = (const float*)d_in[1];
    const float* Wk = (const float*)d_in[2];
    const float* Wv = (const float*)d_in[3];
    const float* Wo = (const float*)d_in[4];
    float* out = (float*)d_out;

    cudaFuncSetAttribute(chunk_attn_k, cudaFuncAttributeMaxDynamicSharedMemorySize, ATTN_SMEM);
    cudaFuncSetAttribute(qkv_gemm, cudaFuncAttributeMaxDynamicSharedMemorySize, SMEM_GEMM_BYTES);
    cudaFuncSetAttribute(o_gemm,   cudaFuncAttributeMaxDynamicSharedMemorySize, SMEM_GEMM_BYTES);

    dim3 thr(256);
    qkv_gemm<<<dim3(18, 8), thr, SMEM_GEMM_BYTES>>>(hs, Wq, Wk, Wv);
    featurize_k<<<dim3(NC, NH, 4), thr>>>();
    chunk_kv_k<<<dim3(2, NC, NH), 288>>>();
    {
        int total = NH * 64 * NW + NH * NW;   // 112320
        prefix_k<<<(total + 255) / 256, 256>>>();
    }
    chunk_attn_k<<<dim3(NC, NH), thr, ATTN_SMEM>>>();
    o_gemm<<<dim3(12, 8), thr, SMEM_GEMM_BYTES>>>(Wo, out);
}

// round 14
// speedup vs baseline: 1.6848x; 1.0712x over previous
#include <cuda_runtime.h>
#include <cstdint>

// Problem constants
#define LL 1024
#define DM 768
#define NH 12
#define FD 16
#define HD 64
#define CH 64
#define NC 16
#define DP 288           // padded expanded feature dim (273 -> 288)
#define NW 144           // DP/2 packed words
#define QK_WORDS (64*NW) // 9216 words per (h,c): [row64][nw144]
#define K2_WORDS (DP*32) // 9216 words per (h,c): [n288][iw32]
#define V_WORDS  (64*32) // 2048 words per (h,c): [d64][iw32]
#define S_ELT    (64*DP) // 18432 fp32 per (h,c), layout [d][n]

// Scratch (static device globals)
__device__ float    g_Q[LL*NH*FD];
__device__ float    g_K[LL*NH*FD];
__device__ float    g_V[LL*DM];
__device__ uint32_t g_Qh [NH*NC*QK_WORDS], g_Ql [NH*NC*QK_WORDS]; // Qf packed along n
__device__ uint32_t g_K1h[NH*NC*QK_WORDS], g_K1l[NH*NC*QK_WORDS]; // Kf packed along n (attn B)
__device__ uint32_t g_K2h[NH*NC*K2_WORDS], g_K2l[NH*NC*K2_WORDS]; // Kf packed along i (kv A)
__device__ uint32_t g_Vh [NH*NC*V_WORDS],  g_Vl [NH*NC*V_WORDS];  // V packed along token
__device__ float    g_S  [NH*NC*S_ELT];   // per-chunk KV sums, [d][n]
__device__ float    g_ks [NH*NC*DP];      // per-chunk k-feature sums
__device__ uint32_t g_Sh [NH*NC*QK_WORDS], g_Sl [NH*NC*QK_WORDS]; // prefix S packed: [d][nw]
__device__ uint32_t g_kh [NH*NC*NW],       g_kl [NH*NC*NW];       // prefix ksum packed
__device__ float    g_Y[LL*DM];

// ---------------------------------------------------------------------------
// bf16 split-pack helpers.  x = hi + lo with hi,lo bf16; dropped lo*lo ~2^-18.
// ---------------------------------------------------------------------------
__device__ __forceinline__ void split_pack(float x0, float x1, uint32_t& hi, uint32_t& lo) {
    uint32_t h;
    asm("cvt.rn.bf16x2.f32 %0, %1, %2;" : "=r"(h) : "f"(x1), "f"(x0));  // hi: x1->upper, x0->lower
    float h0 = __uint_as_float(h << 16);
    float h1 = __uint_as_float(h & 0xffff0000u);
    asm("cvt.rn.bf16x2.f32 %0, %1, %2;" : "=r"(lo) : "f"(x1 - h1), "f"(x0 - h0));
    hi = h;
}
__device__ __forceinline__ void mma_bf16(float c[4], const uint32_t a[4], const uint32_t b[2]) {
    asm volatile("mma.sync.aligned.m16n8k16.row.col.f32.bf16.bf16.f32 "
                 "{%0,%1,%2,%3}, {%4,%5,%6,%7}, {%8,%9}, {%0,%1,%2,%3};\n"
                 : "+f"(c[0]), "+f"(c[1]), "+f"(c[2]), "+f"(c[3])
                 : "r"(a[0]), "r"(a[1]), "r"(a[2]), "r"(a[3]),
                   "r"(b[0]), "r"(b[1]));
}
#define ONES2 0x3F803F80u   // (1.0bf16, 1.0bf16)

// ===========================================================================
// 3xBF16 projection GEMM, 64x64 block tile / 128 threads (4 warps, 2x2),
// warp tile 32x32 = 2x4 m16n8k16 subtiles (same per-warp structure as the
// proven 128x64 version).  Grid doubles -> 2-4 CTAs/SM hides stage latency.
// Packed bf16x2 smem (stride 12 words), double-buffered, register prefetch.
// ===========================================================================
#define GSMBUF 3072                       // words per buffer (Ah/Al/Bh/Bl 768 ea)
#define SMEM_GEMM_BYTES (2 * GSMBUF * 4)  // 24576 B

__device__ __forceinline__ void bf16_body64(const float* __restrict__ A,
                                            const float* __restrict__ B,
                                            float* __restrict__ C,
                                            int N, int K, int bm, int bn,
                                            uint32_t* sm) {
    const int tid  = threadIdx.x, lane = tid & 31, w = tid >> 5;   // 4 warps
    const int wm = w >> 1, wn = w & 1;
    const int gid = lane >> 2, tig = lane & 3;
    const int ar = tid >> 1, aw0 = (tid & 1) * 4;   // A staging: row ar(0..63), words aw0..+3
    const int bnn = tid & 63, bkq = tid >> 6;       // B staging: col bnn, rows bkq*8..+7

    float acc[2][4][4] = {};
    const int nit = K / 16;

    float4 av0 = *(const float4*)&A[(bm + ar) * K + aw0 * 2];
    float4 av1 = *(const float4*)&A[(bm + ar) * K + aw0 * 2 + 4];
    float bv[8];
#pragma unroll
    for (int r = 0; r < 8; r++) bv[r] = B[(bkq * 8 + r) * N + bn + bnn];

    auto cvst = [&](uint32_t* buf, float4 A0, float4 A1, const float* b8) {
        uint32_t* Ah = buf;
        uint32_t* Al = buf + 768;
        uint32_t* Bh = buf + 1536;
        uint32_t* Bl = buf + 2304;
        uint32_t h, l;
        split_pack(A0.x, A0.y, h, l); Ah[ar*12 + aw0 + 0] = h; Al[ar*12 + aw0 + 0] = l;
        split_pack(A0.z, A0.w, h, l); Ah[ar*12 + aw0 + 1] = h; Al[ar*12 + aw0 + 1] = l;
        split_pack(A1.x, A1.y, h, l); Ah[ar*12 + aw0 + 2] = h; Al[ar*12 + aw0 + 2] = l;
        split_pack(A1.z, A1.w, h, l); Ah[ar*12 + aw0 + 3] = h; Al[ar*12 + aw0 + 3] = l;
#pragma unroll
        for (int j = 0; j < 4; j++) {
            split_pack(b8[2*j], b8[2*j+1], h, l);
            Bh[bnn*12 + bkq*4 + j] = h; Bl[bnn*12 + bkq*4 + j] = l;
        }
    };

    cvst(sm, av0, av1, bv);
    __syncthreads();

    for (int it = 0; it < nit; it++) {
        uint32_t* cb = sm + (it & 1) * GSMBUF;
        if (it + 1 < nit) {
            int k0 = (it + 1) * 16;
            av0 = *(const float4*)&A[(bm + ar) * K + k0 + aw0 * 2];
            av1 = *(const float4*)&A[(bm + ar) * K + k0 + aw0 * 2 + 4];
#pragma unroll
            for (int r = 0; r < 8; r++) bv[r] = B[(k0 + bkq * 8 + r) * N + bn + bnn];
        }
        uint32_t* Ah = cb;
        uint32_t* Al = cb + 768;
        uint32_t* Bh = cb + 1536;
        uint32_t* Bl = cb + 2304;
        uint32_t ah[2][4], al_[2][4], bh[4][2], bl_[4][2];
#pragma unroll
        for (int mt = 0; mt < 2; mt++) {
            int rb = wm * 32 + mt * 16;
            ah[mt][0] = Ah[(rb+gid)*12 + tig];     ah[mt][1] = Ah[(rb+gid+8)*12 + tig];
            ah[mt][2] = Ah[(rb+gid)*12 + tig+4];   ah[mt][3] = Ah[(rb+gid+8)*12 + tig+4];
            al_[mt][0] = Al[(rb+gid)*12 + tig];    al_[mt][1] = Al[(rb+gid+8)*12 + tig];
            al_[mt][2] = Al[(rb+gid)*12 + tig+4];  al_[mt][3] = Al[(rb+gid+8)*12 + tig+4];
        }
#pragma unroll
        for (int nt = 0; nt < 4; nt++) {
            int nb = wn * 32 + nt * 8;
            bh[nt][0] = Bh[(nb+gid)*12 + tig];   bh[nt][1] = Bh[(nb+gid)*12 + tig+4];
            bl_[nt][0] = Bl[(nb+gid)*12 + tig];  bl_[nt][1] = Bl[(nb+gid)*12 + tig+4];
        }
#pragma unroll
        for (int mt = 0; mt < 2; mt++)
#pragma unroll
            for (int nt = 0; nt < 4; nt++) {
                mma_bf16(acc[mt][nt], ah[mt],  bh[nt]);
                mma_bf16(acc[mt][nt], ah[mt],  bl_[nt]);
                mma_bf16(acc[mt][nt], al_[mt], bh[nt]);
            }
        if (it + 1 < nit) cvst(sm + ((it + 1) & 1) * GSMBUF, av0, av1, bv);
        __syncthreads();
    }

#pragma unroll
    for (int mt = 0; mt < 2; mt++)
#pragma unroll
        for (int nt = 0; nt < 4; nt++) {
            int row = bm + wm * 32 + mt * 16 + gid;
            int col = bn + wn * 32 + nt * 8 + tig * 2;
            *(float2*)&C[row * N + col]       = make_float2(acc[mt][nt][0], acc[mt][nt][1]);
            *(float2*)&C[(row + 8) * N + col] = make_float2(acc[mt][nt][2], acc[mt][nt][3]);
        }
}

__global__ __launch_bounds__(128) void qkv_gemm(const float* __restrict__ hs,
                                                const float* __restrict__ Wq,
                                                const float* __restrict__ Wk,
                                                const float* __restrict__ Wv) {
    extern __shared__ uint32_t smext[];
    const int bx = blockIdx.x, bm = blockIdx.y * 64;
    const float* B; float* C; int N, bn;
    if (bx < 3)      { B = Wq; C = g_Q; N = NH * FD; bn = bx * 64; }
    else if (bx < 6) { B = Wk; C = g_K; N = NH * FD; bn = (bx - 3) * 64; }
    else             { B = Wv; C = g_V; N = DM;      bn = (bx - 6) * 64; }
    bf16_body64(hs, B, C, N, DM, bm, bn, smext);
}

__global__ __launch_bounds__(128) void o_gemm(const float* __restrict__ Wo,
                                              float* __restrict__ out) {
    extern __shared__ uint32_t smext[];
    bf16_body64(g_Y, Wo, out, DM, DM, blockIdx.y * 64, blockIdx.x * 64, smext);
}

// ===========================================================================
// Featurize + pack.  grid (NC, NH, 4):
//   z=0: Q  -> g_Qh/l  [i][nw]     z=1: K -> g_K1h/l [j][nw]
//   z=2: K  -> g_K2h/l [n][iw]     z=3: V -> g_Vh/l  [d][iw]
// ===========================================================================
__global__ __launch_bounds__(256) void featurize_k() {
    const int c = blockIdx.x, h = blockIdx.y, job = blockIdx.z;
    const int tid = threadIdx.x;

    if (job == 3) {   // V transpose + pack (stride 68: float4-aligned rows)
        __shared__ float vs[64][68];
#pragma unroll
        for (int l = 0; l < 4; l++) {
            int fi = tid + l * 256;
            int i = fi >> 4, d4 = (fi & 15) * 4;
            *(float4*)&vs[i][d4] = *(const float4*)&g_V[(c * CH + i) * DM + h * HD + d4];
        }
        __syncthreads();
        int vb = (h * NC + c) * V_WORDS;
#pragma unroll
        for (int l = 0; l < 8; l++) {
            int wd = tid + l * 256;
            int d = wd >> 5, iw = wd & 31;
            uint32_t hi, lo;
            split_pack(vs[2 * iw][d], vs[2 * iw + 1][d], hi, lo);
            g_Vh[vb + wd] = hi; g_Vl[vb + wd] = lo;
        }
        return;
    }

    __shared__ float xs[64][17];
    const float* __restrict__ src = (job == 0) ? g_Q : g_K;
    for (int idx = tid; idx < CH * FD; idx += 256) {
        int i = idx >> 4, f = idx & 15;
        xs[i][f] = src[(c * CH + i) * (NH * FD) + h * FD + f];
    }
    __syncthreads();
    const float S1 = 0.5f;
    const float S2 = 0.17677669529663687f;
    auto feat = [&](int i, int n) -> float {
        if (n == 0)  return 1.0f;
        if (n <= 16) return xs[i][n - 1] * S1;
        if (n <= 272) { int p = n - 17; return xs[i][p >> 4] * xs[i][p & 15] * S2; }
        return 0.0f;
    };
    const int base = (h * NC + c) * QK_WORDS;
    if (job <= 1) {      // [row i][nw]; incremental i/nw (no div by 144)
        uint32_t* dh = job ? g_K1h : g_Qh;
        uint32_t* dl = job ? g_K1l : g_Ql;
        int i = 0, nw = tid;
        if (nw >= NW) { nw -= NW; i++; }
#pragma unroll 4
        for (int l = 0; l < 36; l++) {
            uint32_t hi, lo;
            split_pack(feat(i, 2 * nw), feat(i, 2 * nw + 1), hi, lo);
            int wd = i * NW + nw;
            dh[base + wd] = hi; dl[base + wd] = lo;
            nw += 256;
            if (nw >= NW) { nw -= NW; i++; }
            if (nw >= NW) { nw -= NW; i++; }
        }
    } else {             // job==2: [n][iw] packed along tokens
#pragma unroll 4
        for (int l = 0; l < 36; l++) {
            int wd = tid + l * 256;
            int n = wd >> 5, iw = wd & 31;
            uint32_t hi, lo;
            split_pack(feat(2 * iw, n), feat(2 * iw + 1, n), hi, lo);
            g_K2h[base + wd] = hi; g_K2l[base + wd] = lo;
        }
    }
}

// ===========================================================================
// chunk_kv (bf16 mma, smem-free): S[d][n] = sum_i Kf[n][i]*V[i][d],
// ksum[n] via ones-B.  grid (2 halves of 144 rows, NC, NH), 288 thr (9 warps).
// ===========================================================================
__global__ __launch_bounds__(288) void chunk_kv_k() {
    const int half = blockIdx.x, c = blockIdx.y, h = blockIdx.z;
    const int tid = threadIdx.x, w = tid >> 5, lane = tid & 31;
    const int gid = lane >> 2, tig = lane & 3;
    const int rbl = half * 144 + w * 16;
    const int kb2 = (h * NC + c) * K2_WORDS;
    const int vb  = (h * NC + c) * V_WORDS;
    float acc[8][4] = {}, acck[4] = {};
    const uint32_t ones[2] = { ONES2, ONES2 };

#pragma unroll
    for (int ks = 0; ks < 4; ks++) {
        const int kw = ks * 8;
        uint32_t ah[4], al_[4];
        ah[0]  = g_K2h[kb2 + (rbl+gid)*32   + kw + tig];
        ah[1]  = g_K2h[kb2 + (rbl+gid+8)*32 + kw + tig];
        ah[2]  = g_K2h[kb2 + (rbl+gid)*32   + kw + tig + 4];
        ah[3]  = g_K2h[kb2 + (rbl+gid+8)*32 + kw + tig + 4];
        al_[0] = g_K2l[kb2 + (rbl+gid)*32   + kw + tig];
        al_[1] = g_K2l[kb2 + (rbl+gid+8)*32 + kw + tig];
        al_[2] = g_K2l[kb2 + (rbl+gid)*32   + kw + tig + 4];
        al_[3] = g_K2l[kb2 + (rbl+gid+8)*32 + kw + tig + 4];
#pragma unroll
        for (int nt = 0; nt < 8; nt++) {
            uint32_t bh[2], bl_[2];
            bh[0]  = g_Vh[vb + (nt*8+gid)*32 + kw + tig];
            bh[1]  = g_Vh[vb + (nt*8+gid)*32 + kw + tig + 4];
            bl_[0] = g_Vl[vb + (nt*8+gid)*32 + kw + tig];
            bl_[1] = g_Vl[vb + (nt*8+gid)*32 + kw + tig + 4];
            mma_bf16(acc[nt], ah,  bh);
            mma_bf16(acc[nt], ah,  bl_);
            mma_bf16(acc[nt], al_, bh);
        }
        mma_bf16(acck, ah,  ones);
        mma_bf16(acck, al_, ones);
    }

    const int sb = (h * NC + c) * S_ELT;
    const int n0 = rbl + gid, n1 = n0 + 8;
#pragma unroll
    for (int nt = 0; nt < 8; nt++) {
        int d0 = nt * 8 + tig * 2;
        g_S[sb + d0 * DP + n0]       = acc[nt][0];
        g_S[sb + (d0 + 1) * DP + n0] = acc[nt][1];
        g_S[sb + d0 * DP + n1]       = acc[nt][2];
        g_S[sb + (d0 + 1) * DP + n1] = acc[nt][3];
    }
    if (tig == 0) {
        g_ks[(h * NC + c) * DP + n0] = acck[0];
        g_ks[(h * NC + c) * DP + n1] = acck[2];
    }
}

// ===========================================================================
// Exclusive prefix over chunks + bf16 pack.  MLP=16 register prefetch
// (measured 7.3-7.5us vs 12.3us serial).
// ===========================================================================
__global__ __launch_bounds__(256) void prefix_k() {
    const int gid = blockIdx.x * 256 + threadIdx.x;
    const int NSEG = NH * 64 * NW;   // 110592
    if (gid < NSEG) {
        int h = gid / (64 * NW), rem = gid % (64 * NW);
        int d = rem / NW, nw = rem % NW;
        const float* src = g_S + h * NC * S_ELT + d * DP + 2 * nw;
        uint32_t* dh = g_Sh + h * NC * QK_WORDS + d * NW + nw;
        uint32_t* dl = g_Sl + h * NC * QK_WORDS + d * NW + nw;
        float2 v[NC];
#pragma unroll
        for (int c = 0; c < NC; c++) v[c] = *(const float2*)&src[c * S_ELT];
        float a0 = 0.f, a1 = 0.f;
#pragma unroll
        for (int c = 0; c < NC; c++) {
            uint32_t hi, lo;
            split_pack(a0, a1, hi, lo);
            dh[c * QK_WORDS] = hi; dl[c * QK_WORDS] = lo;
            a0 += v[c].x; a1 += v[c].y;
        }
    } else if (gid < NSEG + NH * NW) {
        int j = gid - NSEG;
        int h = j / NW, nw = j % NW;
        const float* src = g_ks + h * NC * DP + 2 * nw;
        uint32_t* dh = g_kh + h * NC * NW + nw;
        uint32_t* dl = g_kl + h * NC * NW + nw;
        float v0[NC], v1[NC];
#pragma unroll
        for (int c = 0; c < NC; c++) { v0[c] = src[c * DP]; v1[c] = src[c * DP + 1]; }
        float a0 = 0.f, a1 = 0.f;
#pragma unroll
        for (int c = 0; c < NC; c++) {
            uint32_t hi, lo;
            split_pack(a0, a1, hi, lo);
            dh[c * NW] = hi; dl[c * NW] = lo;
            a0 += v0[c]; a1 += v1[c];
        }
    }
}

// ===========================================================================
// chunk_attn (bf16, staged smem pipeline, scalar LDS fragments — the proven
// round-8 configuration): per (c,h) block, 256 thr, 8 warps (wm 2 x wn 4).
// ===========================================================================
#define ATTN_BUF 4624   // words: Qh 768 Ql 768 Kh 768 Kl 768 Sh 768 Sl 768 ksh 8 ksl 8
#define ATTN_SMEM ((2 * ATTN_BUF + 2 * 2304 + 64) * 4)   // 55680 B
__global__ __launch_bounds__(256, 2) void chunk_attn_k() {
    extern __shared__ uint32_t usm[];
    uint32_t* bufs = usm;                    // 2 x ATTN_BUF
    uint32_t* Ash  = usm + 2 * ATTN_BUF;     // [i][jw] stride 36
    uint32_t* Asl  = Ash + 2304;
    float*    den  = (float*)(Asl + 2304);   // [64]

    const int c = blockIdx.x, h = blockIdx.y;
    const int tid = threadIdx.x, w = tid >> 5, lane = tid & 31;
    const int wm = w >> 2, wn = w & 3;
    const int gid = lane >> 2, tig = lane & 3;

    const int qb  = (h * NC + c) * QK_WORDS;
    const int ksb = (h * NC + c) * NW;
    const int vb  = (h * NC + c) * V_WORDS;

    const uint32_t* gsrc[6] = { g_Qh + qb, g_Ql + qb, g_K1h + qb,
                                g_K1l + qb, g_Sh + qb, g_Sl + qb };
    const int sr = tid >> 3, skw = tid & 7;     // staging coords

    // stage slice 0
    {
#pragma unroll
        for (int o = 0; o < 6; o++)
#pragma unroll
            for (int hf = 0; hf < 2; hf++) {
                int r = sr + hf * 32;
                bufs[o * 768 + r * 12 + skw] = gsrc[o][r * NW + skw];
            }
        if (tid < 8)       bufs[4608 + tid]     = g_kh[ksb + tid];
        else if (tid < 16) bufs[4616 + tid - 8] = g_kl[ksb + tid - 8];
    }
    __syncthreads();

    float aA[2][2][4] = {}, aN[2][2][4] = {}, aD[2][4] = {};
    const uint32_t ones[2] = { ONES2, ONES2 };

    for (int s = 0; s < 18; s++) {
        uint32_t* cb = bufs + (s & 1) * ATTN_BUF;
        uint32_t pf[12]; uint32_t pks = 0;
        if (s + 1 < 18) {
            const int kw0 = (s + 1) * 8;
#pragma unroll
            for (int o = 0; o < 6; o++)
#pragma unroll
                for (int hf = 0; hf < 2; hf++) {
                    int r = sr + hf * 32;
                    pf[o * 2 + hf] = gsrc[o][r * NW + kw0 + skw];
                }
            if (tid < 8)       pks = g_kh[ksb + kw0 + tid];
            else if (tid < 16) pks = g_kl[ksb + kw0 + tid - 8];
        }
        // fragments (scalar LDS, conflict-free via stride 12)
        uint32_t qh[2][4], ql[2][4];
#pragma unroll
        for (int mt = 0; mt < 2; mt++) {
            int rb = wm * 32 + mt * 16;
            qh[mt][0] = cb[(rb+gid)*12 + tig];         qh[mt][1] = cb[(rb+gid+8)*12 + tig];
            qh[mt][2] = cb[(rb+gid)*12 + tig+4];       qh[mt][3] = cb[(rb+gid+8)*12 + tig+4];
            ql[mt][0] = cb[768 + (rb+gid)*12 + tig];   ql[mt][1] = cb[768 + (rb+gid+8)*12 + tig];
            ql[mt][2] = cb[768 + (rb+gid)*12 + tig+4]; ql[mt][3] = cb[768 + (rb+gid+8)*12 + tig+4];
        }
        uint32_t kh[2][2], kl_[2][2], sh[2][2], sl_[2][2];
#pragma unroll
        for (int nt = 0; nt < 2; nt++) {
            int cbn = wn * 16 + nt * 8;
            kh[nt][0]  = cb[1536 + (cbn+gid)*12 + tig]; kh[nt][1]  = cb[1536 + (cbn+gid)*12 + tig+4];
            kl_[nt][0] = cb[2304 + (cbn+gid)*12 + tig]; kl_[nt][1] = cb[2304 + (cbn+gid)*12 + tig+4];
            sh[nt][0]  = cb[3072 + (cbn+gid)*12 + tig]; sh[nt][1]  = cb[3072 + (cbn+gid)*12 + tig+4];
            sl_[nt][0] = cb[3840 + (cbn+gid)*12 + tig]; sl_[nt][1] = cb[3840 + (cbn+gid)*12 + tig+4];
        }
#pragma unroll
        for (int mt = 0; mt < 2; mt++)
#pragma unroll
            for (int nt = 0; nt < 2; nt++) {
                mma_bf16(aA[mt][nt], qh[mt], kh[nt]);
                mma_bf16(aA[mt][nt], qh[mt], kl_[nt]);
                mma_bf16(aA[mt][nt], ql[mt], kh[nt]);
                mma_bf16(aN[mt][nt], qh[mt], sh[nt]);
                mma_bf16(aN[mt][nt], qh[mt], sl_[nt]);
                mma_bf16(aN[mt][nt], ql[mt], sh[nt]);
            }
        if (wn == 0) {
            uint32_t bh2[2] = { cb[4608 + tig], cb[4608 + tig + 4] };
            uint32_t bl2[2] = { cb[4616 + tig], cb[4616 + tig + 4] };
#pragma unroll
            for (int mt = 0; mt < 2; mt++) {
                mma_bf16(aD[mt], qh[mt], bh2);
                mma_bf16(aD[mt], qh[mt], bl2);
                mma_bf16(aD[mt], ql[mt], bh2);
            }
        }
        if (s + 1 < 18) {
            uint32_t* nb2 = bufs + ((s + 1) & 1) * ATTN_BUF;
#pragma unroll
            for (int o = 0; o < 6; o++)
#pragma unroll
                for (int hf = 0; hf < 2; hf++) {
                    int r = sr + hf * 32;
                    nb2[o * 768 + r * 12 + skw] = pf[o * 2 + hf];
                }
            if (tid < 8)       nb2[4608 + tid]     = pks;
            else if (tid < 16) nb2[4616 + tid - 8] = pks;
        }
        __syncthreads();
    }

    // mask scores (keep j <= i), pack, stash to smem
#pragma unroll
    for (int mt = 0; mt < 2; mt++)
#pragma unroll
        for (int nt = 0; nt < 2; nt++) {
            int ri0 = wm * 32 + mt * 16 + gid, ri1 = ri0 + 8;
            int j0 = wn * 16 + nt * 8 + tig * 2;
            int jw = wn * 8 + nt * 4 + tig;
            float x0 = (j0     <= ri0) ? aA[mt][nt][0] : 0.f;
            float x1 = (j0 + 1 <= ri0) ? aA[mt][nt][1] : 0.f;
            float x2 = (j0     <= ri1) ? aA[mt][nt][2] : 0.f;
            float x3 = (j0 + 1 <= ri1) ? aA[mt][nt][3] : 0.f;
            uint32_t hi, lo;
            split_pack(x0, x1, hi, lo); Ash[ri0 * 36 + jw] = hi; Asl[ri0 * 36 + jw] = lo;
            split_pack(x2, x3, hi, lo); Ash[ri1 * 36 + jw] = hi; Asl[ri1 * 36 + jw] = lo;
        }
    __syncthreads();

    // phase 2: num += A @ V ; den += rowsum(A)
#pragma unroll
    for (int ks = 0; ks < 4; ks++) {
        const int kw = ks * 8;
        uint32_t ah[2][4], al2[2][4];
#pragma unroll
        for (int mt = 0; mt < 2; mt++) {
            int rb = wm * 32 + mt * 16;
            ah[mt][0]  = Ash[(rb+gid)*36 + kw + tig];   ah[mt][1]  = Ash[(rb+gid+8)*36 + kw + tig];
            ah[mt][2]  = Ash[(rb+gid)*36 + kw + tig+4]; ah[mt][3]  = Ash[(rb+gid+8)*36 + kw + tig+4];
            al2[mt][0] = Asl[(rb+gid)*36 + kw + tig];   al2[mt][1] = Asl[(rb+gid+8)*36 + kw + tig];
            al2[mt][2] = Asl[(rb+gid)*36 + kw + tig+4]; al2[mt][3] = Asl[(rb+gid+8)*36 + kw + tig+4];
        }
#pragma unroll
        for (int nt = 0; nt < 2; nt++) {
            int d = wn * 16 + nt * 8 + gid;
            uint32_t bh2[2] = { g_Vh[vb + d*32 + kw + tig], g_Vh[vb + d*32 + kw + tig + 4] };
            uint32_t bl2[2] = { g_Vl[vb + d*32 + kw + tig], g_Vl[vb + d*32 + kw + tig + 4] };
#pragma unroll
            for (int mt = 0; mt < 2; mt++) {
                mma_bf16(aN[mt][nt], ah[mt],  bh2);
                mma_bf16(aN[mt][nt], ah[mt],  bl2);
                mma_bf16(aN[mt][nt], al2[mt], bh2);
            }
        }
        if (wn == 0) {
#pragma unroll
            for (int mt = 0; mt < 2; mt++) {
                mma_bf16(aD[mt], ah[mt],  ones);
                mma_bf16(aD[mt], al2[mt], ones);
            }
        }
    }
    if (wn == 0 && tig == 0) {
#pragma unroll
        for (int mt = 0; mt < 2; mt++) {
            den[wm * 32 + mt * 16 + gid]     = aD[mt][0];
            den[wm * 32 + mt * 16 + gid + 8] = aD[mt][2];
        }
    }
    __syncthreads();

    // divide & store
#pragma unroll
    for (int mt = 0; mt < 2; mt++) {
        int ri0 = wm * 32 + mt * 16 + gid, ri1 = ri0 + 8;
        float inv0 = 1.0f / (den[ri0] + 1e-12f);
        float inv1 = 1.0f / (den[ri1] + 1e-12f);
#pragma unroll
        for (int nt = 0; nt < 2; nt++) {
            int cb0 = wn * 16 + nt * 8 + tig * 2;
            *(float2*)&g_Y[(c * CH + ri0) * DM + h * HD + cb0] =
                make_float2(aN[mt][nt][0] * inv0, aN[mt][nt][1] * inv0);
            *(float2*)&g_Y[(c * CH + ri1) * DM + h * HD + cb0] =
                make_float2(aN[mt][nt][2] * inv1, aN[mt][nt][3] * inv1);
        }
    }
}

// ---------------------------------------------------------------------------
extern "C" void kernel_launch(void* const* d_in, const int* in_sizes, int n_in,
                              void* d_out, int out_size) {
    const float* hs = (const float*)d_in[0];
    const float* Wq = (const float*)d_in[1];
    const float* Wk = (const float*)d_in[2];
    const float* Wv = (const float*)d_in[3];
    const float* Wo = (const float*)d_in[4];
    float* out = (float*)d_out;

    cudaFuncSetAttribute(chunk_attn_k, cudaFuncAttributeMaxDynamicSharedMemorySize, ATTN_SMEM);
    cudaFuncSetAttribute(qkv_gemm, cudaFuncAttributeMaxDynamicSharedMemorySize, SMEM_GEMM_BYTES);
    cudaFuncSetAttribute(o_gemm,   cudaFuncAttributeMaxDynamicSharedMemorySize, SMEM_GEMM_BYTES);

    qkv_gemm<<<dim3(18, 16), 128, SMEM_GEMM_BYTES>>>(hs, Wq, Wk, Wv);
    featurize_k<<<dim3(NC, NH, 4), 256>>>();
    chunk_kv_k<<<dim3(2, NC, NH), 288>>>();
    {
        int total = NH * 64 * NW + NH * NW;   // 112320
        prefix_k<<<(total + 255) / 256, 256>>>();
    }
    chunk_attn_k<<<dim3(NC, NH), 256, ATTN_SMEM>>>();
    o_gemm<<<dim3(12, 16), 128, SMEM_GEMM_BYTES>>>(Wo, out);
}